// round 14
// baseline (speedup 1.0000x reference)
#include <cuda_runtime.h>
#include <cuda_bf16.h>
#include <cstdint>

#define NROW 8192
#define DDIM 128
#define THREADS 256
#define NTILE 64                      /* 8192 / 128 */

// ---------------------------------------------------------------------------
// SMEM layout. Row stride 272B (128 bf16 + 8 pad) keeps ldmatrix conflict-free.
// ---------------------------------------------------------------------------
#define ROWB 272
#define SM_A 0
#define SM_B (128 * ROWB)            /* 34816 */
#define SM_SQA (2 * 128 * ROWB)      /* 69632 */
#define SM_SQB (SM_SQA + 512)
#define SMEM_BYTES (SM_SQB + 512)    /* 70656 */

__device__ __forceinline__ uint32_t smem_u32(const void* p) {
    uint32_t a;
    asm("{ .reg .u64 t; cvta.to.shared.u64 t, %1; cvt.u32.u64 %0, t; }"
        : "=r"(a) : "l"(p));
    return a;
}

__device__ __forceinline__ void ldsm4(uint32_t addr, uint32_t r[4]) {
    asm volatile("ldmatrix.sync.aligned.m8n8.x4.shared.b16 {%0,%1,%2,%3}, [%4];"
                 : "=r"(r[0]), "=r"(r[1]), "=r"(r[2]), "=r"(r[3]) : "r"(addr));
}

__device__ __forceinline__ void mma16816(float c[4], const uint32_t a[4],
                                         uint32_t b0, uint32_t b1) {
    asm volatile(
        "mma.sync.aligned.m16n8k16.row.col.f32.bf16.bf16.f32 "
        "{%0,%1,%2,%3}, {%4,%5,%6,%7}, {%8,%9}, {%0,%1,%2,%3};"
        : "+f"(c[0]), "+f"(c[1]), "+f"(c[2]), "+f"(c[3])
        : "r"(a[0]), "r"(a[1]), "r"(a[2]), "r"(a[3]), "r"(b0), "r"(b1));
}

// Convert 8 fp32 (two float4) to 8 bf16 packed in a uint4, and accumulate sum
// of squares into *sq.
__device__ __forceinline__ uint4 cvt8_sq(float4 a, float4 b, float* sq) {
    *sq += a.x * a.x + a.y * a.y + a.z * a.z + a.w * a.w
         + b.x * b.x + b.y * b.y + b.z * b.z + b.w * b.w;
    __nv_bfloat162 p0 = __floats2bfloat162_rn(a.x, a.y);
    __nv_bfloat162 p1 = __floats2bfloat162_rn(a.z, a.w);
    __nv_bfloat162 p2 = __floats2bfloat162_rn(b.x, b.y);
    __nv_bfloat162 p3 = __floats2bfloat162_rn(b.z, b.w);
    uint4 r;
    r.x = *(uint32_t*)&p0; r.y = *(uint32_t*)&p1;
    r.z = *(uint32_t*)&p2; r.w = *(uint32_t*)&p3;
    return r;
}

// ---------------------------------------------------------------------------
// Single fused kernel: one CTA per upper-triangular 128x128 tile.
//  - loads z fp32 (L2-resident), converts to bf16 into smem, and computes the
//    row squared-norms in the same pass (16-lane segmented shuffle reduce);
//  - zero-fills both output tiles up front (dependency-free stores overlap
//    the LDG latency and the whole MMA phase);
//  - mma.sync bf16 Gram; rare value-bearing warp regions patch over zeros.
// ---------------------------------------------------------------------------
extern __shared__ char smem[];

__global__ __launch_bounds__(THREADS, 2)
void pairsim_mma(const float* __restrict__ z, float* __restrict__ out) {
    // Triangular decode: blockIdx.x -> (by, bx) with bx >= by.
    int id = blockIdx.x;
    int by = (int)((2.0f * NTILE + 1.0f
                    - sqrtf((2.0f * NTILE + 1.0f) * (2.0f * NTILE + 1.0f)
                            - 8.0f * (float)id)) * 0.5f);
    while (by > 0 && by * NTILE - (by * (by - 1)) / 2 > id) --by;
    while ((by + 1) * NTILE - ((by + 1) * by) / 2 <= id) ++by;
    const int bx = by + (id - (by * NTILE - (by * (by - 1)) / 2));

    const int brow = by * 128, bcol = bx * 128;
    const uint32_t sb = smem_u32(smem);
    const int tid = threadIdx.x, wid = tid >> 5, lane = tid & 31;
    const int wr = wid & 3, wc = wid >> 2;
    const bool diag = (bx == by);

    float* SQA = (float*)(smem + SM_SQA);
    float* SQB = (float*)(smem + SM_SQB);

    // Load z fp32 -> convert bf16 -> STS; accumulate row sq via 16-lane
    // segmented reduction (each row covered by 16 consecutive threads).
    #pragma unroll
    for (int it = 0; it < 8; ++it) {
        int idx = tid + it * THREADS;        // 0..2047
        int r = idx >> 4, kc = (idx & 15) << 3;
        const float4* za = (const float4*)&z[(size_t)(brow + r) * DDIM + kc];
        const float4* zb = (const float4*)&z[(size_t)(bcol + r) * DDIM + kc];
        float sqa = 0.f, sqb = 0.f;
        uint4 pa = cvt8_sq(za[0], za[1], &sqa);
        uint4 pb = cvt8_sq(zb[0], zb[1], &sqb);
        *(uint4*)(smem + SM_A + r * ROWB + kc * 2) = pa;
        *(uint4*)(smem + SM_B + r * ROWB + kc * 2) = pb;
        #pragma unroll
        for (int off = 8; off > 0; off >>= 1) {
            sqa += __shfl_xor_sync(0xffffffffu, sqa, off, 16);
            sqb += __shfl_xor_sync(0xffffffffu, sqb, off, 16);
        }
        if ((idx & 15) == 0) { SQA[r] = sqa; SQB[r] = sqb; }
    }

    // Dependency-free zero-fill of BOTH output tiles (the common-case bytes).
    {
        const float4 zero = make_float4(0.f, 0.f, 0.f, 0.f);
        const int n0 = tid >> 5;             // row stride 8 per iter
        const int cc = (tid & 31) << 2;
        #pragma unroll
        for (int it = 0; it < 16; ++it) {
            int n = n0 + it * 8;
            *(float4*)&out[(size_t)(brow + n) * NROW + bcol + cc] = zero;
        }
        if (!diag) {
            #pragma unroll
            for (int it = 0; it < 16; ++it) {
                int n = n0 + it * 8;
                *(float4*)&out[(size_t)(bcol + n) * NROW + brow + cc] = zero;
            }
        }
    }

    __syncthreads();   // tiles + sq ready in smem; orders zero-fill vs patches

    // ldmatrix lane base addresses.
    const uint32_t aBase = sb + SM_A + (wr * 32 + (lane & 15)) * ROWB
                         + ((lane >> 4) << 4);
    const uint32_t bBase = sb + SM_B
                         + (wc * 64 + ((lane & 7) | ((lane >> 4) << 3))) * ROWB
                         + (((lane >> 3) & 1) << 4);

    float acc[2][8][4];
    #pragma unroll
    for (int mt = 0; mt < 2; ++mt)
        #pragma unroll
        for (int nt = 0; nt < 8; ++nt)
            #pragma unroll
            for (int c = 0; c < 4; ++c) acc[mt][nt][c] = 0.0f;

    #pragma unroll
    for (int ks = 0; ks < 8; ++ks) {
        uint32_t aF[2][4], bF[4][4];
        ldsm4(aBase + ks * 32, aF[0]);
        ldsm4(aBase + 16 * ROWB + ks * 32, aF[1]);
        #pragma unroll
        for (int p = 0; p < 4; ++p) ldsm4(bBase + p * 16 * ROWB + ks * 32, bF[p]);
        #pragma unroll
        for (int mt = 0; mt < 2; ++mt)
            #pragma unroll
            for (int p = 0; p < 4; ++p) {
                mma16816(acc[mt][2 * p],     aF[mt], bF[p][0], bF[p][1]);
                mma16816(acc[mt][2 * p + 1], aF[mt], bF[p][2], bF[p][3]);
            }
    }

    // Epilogue: d2 = sqa + sqb - 2*gram.
    const int qr = lane >> 2;            // 0..7
    const int qc = (lane & 3) << 1;      // 0,2,4,6
    float sqa_r[4], sqb_c[16];
    #pragma unroll
    for (int mt = 0; mt < 2; ++mt)
        #pragma unroll
        for (int h = 0; h < 2; ++h)
            sqa_r[mt * 2 + h] = SQA[wr * 32 + mt * 16 + qr + h * 8];
    #pragma unroll
    for (int nt = 0; nt < 8; ++nt) {
        sqb_c[2 * nt]     = SQB[wc * 64 + nt * 8 + qc];
        sqb_c[2 * nt + 1] = SQB[wc * 64 + nt * 8 + qc + 1];
    }

    float vmin = 3.4e38f;
    #pragma unroll
    for (int mt = 0; mt < 2; ++mt)
        #pragma unroll
        for (int nt = 0; nt < 8; ++nt)
            #pragma unroll
            for (int c = 0; c < 4; ++c) {
                float s = sqa_r[mt * 2 + (c >> 1)] + sqb_c[2 * nt + (c & 1)];
                float d2 = fmaf(-2.0f, acc[mt][nt][c], s);
                acc[mt][nt][c] = d2;
                vmin = fminf(vmin, d2);
            }

    // Rare: this warp's 32x64 region holds a representable value (or diag 1s).
    const bool crossDiag = diag && ((wr >> 1) == wc);
    const bool anyv = crossDiag | __any_sync(0xffffffffu, vmin < 88.0f);
    if (!anyv) return;                   // zeros already in place

    #pragma unroll
    for (int mt = 0; mt < 2; ++mt)
        #pragma unroll
        for (int nt = 0; nt < 8; ++nt)
            #pragma unroll
            for (int c = 0; c < 4; ++c) {
                float d2 = fmaxf(acc[mt][nt][c], 0.0f);
                float v = (d2 < 88.0f) ? __expf(-d2) : 0.0f;
                int m = brow + wr * 32 + mt * 16 + qr + ((c >> 1) << 3);
                int n = bcol + wc * 64 + nt * 8 + qc + (c & 1);
                if (m == n) v = 1.0f;    // exact diagonal
                acc[mt][nt][c] = v;
            }

    // Patch direct region (fragment-layout float2 stores).
    #pragma unroll
    for (int mt = 0; mt < 2; ++mt)
        #pragma unroll
        for (int h = 0; h < 2; ++h) {
            int m_loc = wr * 32 + mt * 16 + qr + h * 8;
            size_t rowp = (size_t)(brow + m_loc) * NROW + bcol + wc * 64;
            #pragma unroll
            for (int nt = 0; nt < 8; ++nt)
                *(float2*)&out[rowp + nt * 8 + qc] =
                    make_float2(acc[mt][nt][2 * h], acc[mt][nt][2 * h + 1]);
        }

    // Patch mirror region (scalar transposed scatter).
    if (!diag) {
        #pragma unroll
        for (int mt = 0; mt < 2; ++mt)
            #pragma unroll
            for (int nt = 0; nt < 8; ++nt)
                #pragma unroll
                for (int c = 0; c < 4; ++c) {
                    int m = brow + wr * 32 + mt * 16 + qr + ((c >> 1) << 3);
                    int n = bcol + wc * 64 + nt * 8 + qc + (c & 1);
                    out[(size_t)n * NROW + m] = acc[mt][nt][c];
                }
    }
}

// ---------------------------------------------------------------------------
extern "C" void kernel_launch(void* const* d_in, const int* in_sizes, int n_in,
                              void* d_out, int out_size) {
    const float* z = (const float*)d_in[0];
    float* out = (float*)d_out;
    (void)in_sizes; (void)n_in; (void)out_size;

    cudaFuncSetAttribute(pairsim_mma,
                         cudaFuncAttributeMaxDynamicSharedMemorySize, SMEM_BYTES);

    const int ntri = NTILE * (NTILE + 1) / 2;    // 2080
    pairsim_mma<<<ntri, THREADS, SMEM_BYTES>>>(z, out);
}